// round 16
// baseline (speedup 1.0000x reference)
#include <cuda_runtime.h>
#include <math.h>

#define C_DIM 1280
#define HW    9216
#define WIMG  96
#define N_ID  16
#define D_IN  512
#define B_SZ  8
#define M_ROWS 128
#define PCTAS 128

// ---------------- scratch ----------------
__device__ float g_h[M_ROWS * C_DIM];          // GELU hidden
__device__ float g_p[M_ROWS * C_DIM];          // mlp2 out (+bias), pre-norm
__device__ float g_pt[B_SZ * C_DIM * N_ID];    // projected [b][c][n]
__device__ unsigned g_arrive;                   // grid-barrier counter (self-resetting)
__device__ unsigned g_release;                  // grid-barrier phase flag

// ---------------- f32x2 helpers ----------------
__device__ __forceinline__ unsigned long long fma2(unsigned long long a,
                                                   unsigned long long b,
                                                   unsigned long long c) {
    unsigned long long d;
    asm("fma.rn.f32x2 %0, %1, %2, %3;" : "=l"(d) : "l"(a), "l"(b), "l"(c));
    return d;
}
__device__ __forceinline__ unsigned long long packf2(float lo, float hi) {
    unsigned long long r;
    asm("mov.b64 %0, {%1, %2};" : "=l"(r) : "f"(lo), "f"(hi));
    return r;
}
__device__ __forceinline__ float2 unpackf2(unsigned long long v) {
    float2 r;
    asm("mov.b64 {%0, %1}, %2;" : "=f"(r.x), "=f"(r.y) : "l"(v));
    return r;
}

// ---------------- software grid barrier (all PCTAS resident in wave 1) ----------
__device__ __forceinline__ void grid_barrier(int phase) {
    __syncthreads();
    if (threadIdx.x == 0) {
        __threadfence();
        unsigned prev = atomicAdd(&g_arrive, 1u);
        if (prev == (unsigned)((phase + 1) * PCTAS - 1)) {
            *(volatile unsigned*)&g_release = (unsigned)(phase + 1);
        }
        while (*(volatile unsigned*)&g_release < (unsigned)(phase + 1)) { }
        __threadfence();
    }
    __syncthreads();
}

// ---------------- 32x64 GEMM tile body (256 thr, 8 outputs/thread) ----------------
__device__ __forceinline__ void gemm_body(float (*sAt)[34], float (*sB)[68],
                                          const float* __restrict__ A, int ldA,
                                          const float* __restrict__ Wm,
                                          const float* __restrict__ bias, bool gelu,
                                          float* __restrict__ Out,
                                          int K, int rowBase, int colBase, int t) {
    int tj = t & 15;
    int tr = t >> 4;
    unsigned long long acc[2][2];
    acc[0][0] = acc[0][1] = acc[1][0] = acc[1][1] = 0ull;

    for (int kt = 0; kt < K; kt += 32) {
#pragma unroll
        for (int s = 0; s < 4; s++) {          // A tile: 32 rows x 32 k
            int idx = t + s * 256;
            int row = idx >> 5, kk = idx & 31;
            sAt[kk][row] = A[(size_t)(rowBase + row) * ldA + kt + kk];
        }
#pragma unroll
        for (int s = 0; s < 8; s++) {          // B tile: 32 k x 64 cols
            int idx = t + s * 256;
            int r = idx >> 6, c = idx & 63;
            sB[r][c] = Wm[(size_t)(kt + r) * C_DIM + colBase + c];
        }
        __syncthreads();
#pragma unroll
        for (int k = 0; k < 32; k++) {
            float2 av = *(const float2*)&sAt[k][tr * 2];
            ulonglong2 bv = *(const ulonglong2*)&sB[k][tj * 4];
            unsigned long long a0 = packf2(av.x, av.x);
            unsigned long long a1 = packf2(av.y, av.y);
            acc[0][0] = fma2(a0, bv.x, acc[0][0]);
            acc[0][1] = fma2(a0, bv.y, acc[0][1]);
            acc[1][0] = fma2(a1, bv.x, acc[1][0]);
            acc[1][1] = fma2(a1, bv.y, acc[1][1]);
        }
        __syncthreads();
    }
#pragma unroll
    for (int r = 0; r < 2; r++) {
        float2 v0 = unpackf2(acc[r][0]);
        float2 v1 = unpackf2(acc[r][1]);
        float vals[4] = {v0.x, v0.y, v1.x, v1.y};
        int row = rowBase + tr * 2 + r;
        int col = colBase + tj * 4;
        float4 o;
        float* ov = (float*)&o;
#pragma unroll
        for (int i = 0; i < 4; i++) {
            float v = vals[i] + bias[col + i];
            if (gelu) v = 0.5f * v * (1.f + erff(v * 0.70710678f));
            ov[i] = v;
        }
        *(float4*)&Out[(size_t)row * C_DIM + col] = o;
    }
}

// ---------------- persistent MLP chain: mlp1 -> bar -> mlp2 -> bar -> norm ----------
__global__ __launch_bounds__(256) void mlp_chain_kernel(const float* __restrict__ E,
                                                        const float* __restrict__ W1,
                                                        const float* __restrict__ b1,
                                                        const float* __restrict__ W2,
                                                        const float* __restrict__ b2) {
    __shared__ float sAt[32][34];
    __shared__ float sB[32][68];
    __shared__ float sw[8];
    int t = threadIdx.x;
    int cta = blockIdx.x;

    // phase 1: mlp1 (GELU) — 80 tiles of 32x64, K=512
    if (cta < 80) {
        int rowBase = (cta / 20) * 32;
        int colBase = (cta % 20) * 64;
        gemm_body(sAt, sB, E, D_IN, W1, b1, true, g_h, D_IN, rowBase, colBase, t);
    }
    grid_barrier(0);

    // phase 2: mlp2 (+b2) — 80 tiles of 32x64, K=1280
    if (cta < 80) {
        int rowBase = (cta / 20) * 32;
        int colBase = (cta % 20) * 64;
        gemm_body(sAt, sB, g_h, C_DIM, W2, b2, false, g_p, C_DIM, rowBase, colBase, t);
    }
    grid_barrier(1);

    // phase 3: row-normalize + transpose -> g_pt[b][c][16]
    {
        int r = cta;                      // 0..127
        int b = r >> 4, n = r & 15;
        float v[5];
        float ss = 0.f;
#pragma unroll
        for (int i = 0; i < 5; i++) {
            int c = t + i * 256;
            float xv = g_p[(size_t)r * C_DIM + c];
            v[i] = xv;
            ss = fmaf(xv, xv, ss);
        }
#pragma unroll
        for (int o = 16; o > 0; o >>= 1) ss += __shfl_xor_sync(0xffffffffu, ss, o);
        if ((t & 31) == 0) sw[t >> 5] = ss;
        __syncthreads();
        float tot = 0.f;
#pragma unroll
        for (int i = 0; i < 8; i++) tot += sw[i];
        float scale = 35.7770876f / (sqrtf(tot) + 1e-6f);   // sqrt(1280)
#pragma unroll
        for (int i = 0; i < 5; i++) {
            int c = t + i * 256;
            g_pt[((size_t)b * C_DIM + c) * N_ID + n] = v[i] * scale;
        }
    }

    // final arrival: last CTA resets barrier state for the next graph replay
    __syncthreads();
    if (t == 0) {
        unsigned prev = atomicAdd(&g_arrive, 1u);
        if (prev == (unsigned)(3 * PCTAS - 1)) {
            *(volatile unsigned*)&g_release = 0u;
            *(volatile unsigned*)&g_arrive = 0u;
            __threadfence();
        }
    }
}

// ---------------- fused main kernel (R14 champion: 4-stage, UNR=10) ----------------
// 128 thr, 2 px/thread, 256 px/CTA, grid 288 (36 blk/batch), 80KB smem, 2 CTAs/SM
#define UNR 10
__global__ __launch_bounds__(128, 2) void fused_kernel(const float* __restrict__ hidden,
                                                       const float* __restrict__ bboxes,
                                                       float* __restrict__ out) {
    extern __shared__ float sp[];               // [1280][16]
    __shared__ int sx1[N_ID], sy1[N_ID], sx2[N_ID], sy2[N_ID], semp[N_ID];

    int t = threadIdx.x;
    int blk = blockIdx.x;
    int b = blk / 36;
    int px = (blk % 36) * 256 + 2 * t;          // even; pair never crosses a row

    const float4* src = (const float4*)(g_pt + (size_t)b * C_DIM * N_ID);
    float4* dst = (float4*)sp;
#pragma unroll
    for (int i = 0; i < 40; i++) dst[t + i * 128] = src[t + i * 128];

    if (t < N_ID) {
        float bx1 = bboxes[t * 4 + 0] * 96.f;
        float by1 = bboxes[t * 4 + 1] * 96.f;
        float bx2 = bboxes[t * 4 + 2] * 96.f;
        float by2 = bboxes[t * 4 + 3] * 96.f;
        int X1 = (int)floorf(fminf(fmaxf(bx1, 0.f), 96.f));
        int Y1 = (int)floorf(fminf(fmaxf(by1, 0.f), 96.f));
        int X2 = (int)floorf(fminf(fmaxf(bx2, 0.f), 96.f));
        int Y2 = (int)floorf(fminf(fmaxf(by2, 0.f), 96.f));
        sx1[t] = X1; sy1[t] = Y1; sx2[t] = X2; sy2[t] = Y2;
        semp[t] = (X1 >= X2) || (Y1 >= Y2);
    }
    __syncthreads();

    int allempty = 1;
#pragma unroll
    for (int n = 0; n < N_ID; n++) allempty &= semp[n];

    int y = px / WIMG;
    int x = px - y * WIMG;
    const float* hp = hidden + (size_t)b * C_DIM * HW + px;

    // ---- pass 1: sumsq + 16 dots for 2 px; 4-stage pipeline ----
    unsigned long long acc0[8], acc1[8];
#pragma unroll
    for (int k = 0; k < 8; k++) { acc0[k] = 0ull; acc1[k] = 0ull; }
    float ss0 = 0.f, ss1 = 0.f;

    float2 h0[UNR], h1[UNR], h2[UNR], h3[UNR];

#define LOADB(BUF, CB)                                                           \
    {                                                                            \
        _Pragma("unroll")                                                        \
        for (int i = 0; i < UNR; i++)                                            \
            BUF[i] = *(const float2*)(hp + (size_t)((CB) + i) * HW);             \
    }
#define LOADB_G(BUF, CB)                                                         \
    if ((CB) < C_DIM) LOADB(BUF, CB)

#define P1_COMPUTE(HBUF, CB)                                                     \
    {                                                                            \
        _Pragma("unroll")                                                        \
        for (int i = 0; i < UNR; i++) {                                          \
            ss0 = fmaf(HBUF[i].x, HBUF[i].x, ss0);                               \
            ss1 = fmaf(HBUF[i].y, HBUF[i].y, ss1);                               \
            unsigned long long hx = packf2(HBUF[i].x, HBUF[i].x);                \
            unsigned long long hy = packf2(HBUF[i].y, HBUF[i].y);                \
            const ulonglong2* p2 = (const ulonglong2*)(sp + (((CB) + i) << 4));  \
            ulonglong2 q0 = p2[0], q1 = p2[1], q2 = p2[2], q3 = p2[3];           \
            acc0[0] = fma2(hx, q0.x, acc0[0]);  acc1[0] = fma2(hy, q0.x, acc1[0]); \
            acc0[1] = fma2(hx, q0.y, acc0[1]);  acc1[1] = fma2(hy, q0.y, acc1[1]); \
            acc0[2] = fma2(hx, q1.x, acc0[2]);  acc1[2] = fma2(hy, q1.x, acc1[2]); \
            acc0[3] = fma2(hx, q1.y, acc0[3]);  acc1[3] = fma2(hy, q1.y, acc1[3]); \
            acc0[4] = fma2(hx, q2.x, acc0[4]);  acc1[4] = fma2(hy, q2.x, acc1[4]); \
            acc0[5] = fma2(hx, q2.y, acc0[5]);  acc1[5] = fma2(hy, q2.y, acc1[5]); \
            acc0[6] = fma2(hx, q3.x, acc0[6]);  acc1[6] = fma2(hy, q3.x, acc1[6]); \
            acc0[7] = fma2(hx, q3.y, acc0[7]);  acc1[7] = fma2(hy, q3.y, acc1[7]); \
        }                                                                        \
    }

    LOADB(h0, 0)
    LOADB(h1, UNR)
    LOADB(h2, 2 * UNR)
    for (int cb = 0; cb < C_DIM; cb += 4 * UNR) {
        LOADB(h3, cb + 3 * UNR)
        P1_COMPUTE(h0, cb)
        LOADB_G(h0, cb + 4 * UNR)
        P1_COMPUTE(h1, cb + UNR)
        LOADB_G(h1, cb + 5 * UNR)
        P1_COMPUTE(h2, cb + 2 * UNR)
        LOADB_G(h2, cb + 6 * UNR)
        P1_COMPUTE(h3, cb + 3 * UNR)
    }

    // ---- weights for both pixels ----
    const float invT = 1.999996f;               // 1/(0.5+1e-6)
    float inv0 = invT / (sqrtf(ss0) + 1e-6f);
    float inv1 = invT / (sqrtf(ss1) + 1e-6f);
    float w0[N_ID], w1[N_ID];
    float sum0 = 0.f, sum1 = 0.f;
#pragma unroll
    for (int k = 0; k < 8; k++) {
        float2 d0 = unpackf2(acc0[k]);
        float2 d1 = unpackf2(acc1[k]);
#pragma unroll
        for (int j = 0; j < 2; j++) {
            int n = 2 * k + j;
            float da = (j == 0) ? d0.x : d0.y;
            float db = (j == 0) ? d1.x : d1.y;
            int ybox = (y >= sy1[n]) & (y < sy2[n]);
            int m0 = allempty | (ybox & (x >= sx1[n]) & (x < sx2[n]));
            int m1 = allempty | (ybox & ((x + 1) >= sx1[n]) & ((x + 1) < sx2[n]));
            float s0 = 1.f / (1.f + __expf(-da * inv0));
            float s1 = 1.f / (1.f + __expf(-db * inv1));
            float wv0 = m0 ? s0 : 0.f;
            float wv1 = m1 ? s1 : 0.f;
            w0[n] = wv0; sum0 += wv0;
            w1[n] = wv1; sum1 += wv1;
        }
    }
    float is0 = 1.f / (sum0 + 1e-6f);
    float is1 = 1.f / (sum1 + 1e-6f);
    unsigned long long wp0[8], wp1[8];
#pragma unroll
    for (int k = 0; k < 8; k++) {
        wp0[k] = packf2(__powf(w0[2 * k] * is0, 1.2f), __powf(w0[2 * k + 1] * is0, 1.2f));
        wp1[k] = packf2(__powf(w1[2 * k] * is1, 1.2f), __powf(w1[2 * k + 1] * is1, 1.2f));
    }

    // ---- pass 2: out = hidden + 1.5*sum_n w[n]*p[n,c]; 4-stage pipeline ----
    float* op = out + (size_t)b * C_DIM * HW + px;

#define P2_COMPUTE(HBUF, CB)                                                     \
    {                                                                            \
        _Pragma("unroll")                                                        \
        for (int i = 0; i < UNR; i++) {                                          \
            const ulonglong2* pq = (const ulonglong2*)(sp + (((CB) + i) << 4));  \
            ulonglong2 q0 = pq[0], q1 = pq[1], q2 = pq[2], q3 = pq[3];           \
            unsigned long long s0 = 0ull, s1 = 0ull;                             \
            s0 = fma2(wp0[0], q0.x, s0);  s1 = fma2(wp1[0], q0.x, s1);           \
            s0 = fma2(wp0[1], q0.y, s0);  s1 = fma2(wp1[1], q0.y, s1);           \
            s0 = fma2(wp0[2], q1.x, s0);  s1 = fma2(wp1[2], q1.x, s1);           \
            s0 = fma2(wp0[3], q1.y, s0);  s1 = fma2(wp1[3], q1.y, s1);           \
            s0 = fma2(wp0[4], q2.x, s0);  s1 = fma2(wp1[4], q2.x, s1);           \
            s0 = fma2(wp0[5], q2.y, s0);  s1 = fma2(wp1[5], q2.y, s1);           \
            s0 = fma2(wp0[6], q3.x, s0);  s1 = fma2(wp1[6], q3.x, s1);           \
            s0 = fma2(wp0[7], q3.y, s0);  s1 = fma2(wp1[7], q3.y, s1);           \
            float2 a0 = unpackf2(s0), a1 = unpackf2(s1);                         \
            float2 o;                                                            \
            o.x = fmaf(1.5f, a0.x + a0.y, HBUF[i].x);                            \
            o.y = fmaf(1.5f, a1.x + a1.y, HBUF[i].y);                            \
            __stcs((float2*)(op + (size_t)((CB) + i) * HW), o);                  \
        }                                                                        \
    }

    LOADB(h0, 0)
    LOADB(h1, UNR)
    LOADB(h2, 2 * UNR)
    for (int cb = 0; cb < C_DIM; cb += 4 * UNR) {
        LOADB(h3, cb + 3 * UNR)
        P2_COMPUTE(h0, cb)
        LOADB_G(h0, cb + 4 * UNR)
        P2_COMPUTE(h1, cb + UNR)
        LOADB_G(h1, cb + 5 * UNR)
        P2_COMPUTE(h2, cb + 2 * UNR)
        LOADB_G(h2, cb + 6 * UNR)
        P2_COMPUTE(h3, cb + 3 * UNR)
    }
}

// ---------------- launch ----------------
extern "C" void kernel_launch(void* const* d_in, const int* in_sizes, int n_in,
                              void* d_out, int out_size) {
    const float* hidden = (const float*)d_in[0];
    const float* emb    = (const float*)d_in[1];
    const float* bbox   = (const float*)d_in[2];
    const float* W1     = (const float*)d_in[3];
    const float* b1v    = (const float*)d_in[4];
    const float* W2     = (const float*)d_in[5];
    const float* b2v    = (const float*)d_in[6];
    float* outp = (float*)d_out;

    mlp_chain_kernel<<<PCTAS, 256>>>(emb, W1, b1v, W2, b2v);

    cudaFuncSetAttribute(fused_kernel, cudaFuncAttributeMaxDynamicSharedMemorySize,
                         C_DIM * N_ID * (int)sizeof(float));
    fused_kernel<<<288, 128, C_DIM * N_ID * sizeof(float)>>>(hidden, bbox, outp);
}